// round 4
// baseline (speedup 1.0000x reference)
#include <cuda_runtime.h>
#include <math.h>

#define NN 50000
#define NE 600000
#define D  128
#define NH 3

// ---------------- scratch (static device globals; no allocation) ----------------
__device__ __align__(16) float    g_X1[(size_t)NN * D];     // x @ W_lin + b
__device__ __align__(16) float    g_H[(size_t)NH * NN * D]; // per-head projections
__device__ float    g_ssrc[NH * NN];                        // H @ att_src
__device__ float    g_sdst[NH * NN];                        // H @ att_dst
__device__ unsigned g_emax[NH * NN];                        // encoded segment max
__device__ float    g_den[NH * NN];                         // softmax denominator
__device__ __align__(16) float g_ev[(size_t)NH * NE];       // per-edge logit -> exp
__device__ int      g_ei64;                                 // edge_index is int64?
__device__ int      g_eid64;                                // edge_ids  is int64?

// order-preserving float <-> uint for atomicMax
__device__ __forceinline__ unsigned f2u_ord(float f) {
    unsigned b = __float_as_uint(f);
    return (b & 0x80000000u) ? ~b : (b | 0x80000000u);
}
__device__ __forceinline__ float u2f_ord(unsigned u) {
    return (u & 0x80000000u) ? __uint_as_float(u ^ 0x80000000u) : __uint_as_float(~u);
}

// dtype-robust index load: if is64, element i of an int64 array, else int32.
__device__ __forceinline__ int load_idx(const void* p, int is64, long long i) {
    if (is64) return (int)((const long long*)p)[i];
    return ((const int*)p)[i];
}

// ---------------- dtype detection ----------------
// For little-endian int64 values in [0, 2^31), every odd 32-bit word is 0.
// For int32 payloads (random ids), 64 consecutive odd words all-zero is ~impossible.
__global__ void detect_dtype(const unsigned* __restrict__ ei_raw,
                             const unsigned* __restrict__ eid_raw) {
    int lane = threadIdx.x;                     // 64 threads
    unsigned a = ei_raw[2 * lane + 1];
    unsigned b = eid_raw[2 * lane + 1];
    unsigned ba = __ballot_sync(0xffffffffu, a == 0u);
    unsigned bb = __ballot_sync(0xffffffffu, b == 0u);
    __shared__ unsigned sa[2], sb[2];
    if ((threadIdx.x & 31) == 0) { sa[threadIdx.x >> 5] = ba; sb[threadIdx.x >> 5] = bb; }
    __syncthreads();
    if (threadIdx.x == 0) {
        g_ei64  = (sa[0] == 0xffffffffu && sa[1] == 0xffffffffu) ? 1 : 0;
        g_eid64 = (sb[0] == 0xffffffffu && sb[1] == 0xffffffffu) ? 1 : 0;
    }
}

// ---------------- init: out = mean(bias_heads), softmax state ----------------
__global__ void __launch_bounds__(256) init_kernel(float* __restrict__ out,
                                                   const float* __restrict__ bh) {
    int i = blockIdx.x * 256 + threadIdx.x;
    if (i < NN * D) {
        int d = i & (D - 1);
        out[i] = (bh[d] + bh[D + d] + bh[2 * D + d]) * (1.0f / 3.0f);
    }
    if (i < NH * NN) {
        g_emax[i] = 0x007FFFFFu;   // encoded -inf
        g_den[i]  = 0.0f;
    }
}

// ---------------- fp32 GEMM core: C[M,128] = A[M,128] @ B[128,128] (+bias) ----------------
// 256 threads, 128x128 tile, BK=16, 8x8 micro-tile.
__device__ __forceinline__ void gemm128_body(
    const float* __restrict__ A, const float* __restrict__ B,
    const float* __restrict__ bias, float* __restrict__ C, int M)
{
    __shared__ float As[16][132];   // [k][m], padded (132*4B % 16 == 0)
    __shared__ float Bs[16][128];   // [k][n]

    const int tid = threadIdx.x;
    const int tx  = tid & 15;        // col group
    const int ty  = tid >> 4;        // row group
    const int row0 = blockIdx.x * 128;

    float acc[8][8];
#pragma unroll
    for (int i = 0; i < 8; i++)
#pragma unroll
        for (int j = 0; j < 8; j++) acc[i][j] = 0.0f;

    for (int k0 = 0; k0 < 128; k0 += 16) {
#pragma unroll
        for (int i = 0; i < 2; i++) {
            int idx = tid + i * 256;          // 0..511 float4 slots
            int r   = idx >> 2;               // 0..127
            int kq  = (idx & 3) << 2;         // 0,4,8,12
            int gr  = row0 + r;
            float4 v = make_float4(0.f, 0.f, 0.f, 0.f);
            if (gr < M) v = *(const float4*)(A + (long long)gr * D + k0 + kq);
            As[kq + 0][r] = v.x; As[kq + 1][r] = v.y;
            As[kq + 2][r] = v.z; As[kq + 3][r] = v.w;
        }
#pragma unroll
        for (int i = 0; i < 2; i++) {
            int idx = tid + i * 256;
            int kr  = idx >> 5;               // 0..15
            int nq  = (idx & 31) << 2;        // 0..124
            *(float4*)&Bs[kr][nq] = *(const float4*)(B + (long long)(k0 + kr) * D + nq);
        }
        __syncthreads();

#pragma unroll
        for (int k = 0; k < 16; k++) {
            float a[8], b[8];
            *(float4*)&a[0] = *(float4*)&As[k][ty * 8];
            *(float4*)&a[4] = *(float4*)&As[k][ty * 8 + 4];
            *(float4*)&b[0] = *(float4*)&Bs[k][tx * 8];
            *(float4*)&b[4] = *(float4*)&Bs[k][tx * 8 + 4];
#pragma unroll
            for (int i = 0; i < 8; i++)
#pragma unroll
                for (int j = 0; j < 8; j++)
                    acc[i][j] = fmaf(a[i], b[j], acc[i][j]);
        }
        __syncthreads();
    }

    float bv[8];
#pragma unroll
    for (int j = 0; j < 8; j++) bv[j] = bias ? bias[tx * 8 + j] : 0.0f;

#pragma unroll
    for (int i = 0; i < 8; i++) {
        int r = row0 + ty * 8 + i;
        if (r < M) {
            float4 o0 = make_float4(acc[i][0] + bv[0], acc[i][1] + bv[1],
                                    acc[i][2] + bv[2], acc[i][3] + bv[3]);
            float4 o1 = make_float4(acc[i][4] + bv[4], acc[i][5] + bv[5],
                                    acc[i][6] + bv[6], acc[i][7] + bv[7]);
            *(float4*)(C + (long long)r * D + tx * 8)     = o0;
            *(float4*)(C + (long long)r * D + tx * 8 + 4) = o1;
        }
    }
}

// X1 = x @ W_lin + b_lin   (writes g_X1 directly; no symbol lookup needed)
__global__ void __launch_bounds__(256) gemm_lin(const float* __restrict__ x,
                                                const float* __restrict__ Wlin,
                                                const float* __restrict__ blin) {
    gemm128_body(x, Wlin, blin, g_X1, NN);
}

// H_h = X1 @ W_h  for head = blockIdx.y
__global__ void __launch_bounds__(256) gemm_heads(const float* __restrict__ Wh) {
    gemm128_body(g_X1, Wh + (long long)blockIdx.y * D * D, nullptr,
                 g_H + (size_t)blockIdx.y * NN * D, NN);
}

// ---------------- attention scores: s_src/s_dst = H @ att vectors ----------------
__global__ void __launch_bounds__(256) attn_scores(const float* __restrict__ asrc,
                                                   const float* __restrict__ adst) {
    int w    = (blockIdx.x * 256 + threadIdx.x) >> 5;   // one warp per (head,node)
    int lane = threadIdx.x & 31;
    if (w >= NH * NN) return;
    int h = w / NN;
    int n = w - h * NN;

    float4 hv = ((const float4*)(g_H + ((size_t)h * NN + n) * D))[lane];
    float4 as = ((const float4*)(asrc + h * D))[lane];
    float4 ad = ((const float4*)(adst + h * D))[lane];
    float s1 = hv.x * as.x + hv.y * as.y + hv.z * as.z + hv.w * as.w;
    float s2 = hv.x * ad.x + hv.y * ad.y + hv.z * ad.z + hv.w * ad.w;
#pragma unroll
    for (int o = 16; o; o >>= 1) {
        s1 += __shfl_xor_sync(0xffffffffu, s1, o);
        s2 += __shfl_xor_sync(0xffffffffu, s2, o);
    }
    if (lane == 0) { g_ssrc[w] = s1; g_sdst[w] = s2; }
}

// ---------------- edge pass 1: logits + segment max ----------------
__global__ void __launch_bounds__(256) edge_pass1(const void* __restrict__ ei) {
    int idx = blockIdx.x * 256 + threadIdx.x;
    if (idx >= NH * NE) return;
    int h = idx / NE;
    int e = idx - h * NE;
    int is64 = g_ei64;
    int src = load_idx(ei, is64, e);
    int dst = load_idx(ei, is64, NE + e);
    float v = g_ssrc[h * NN + src] + g_sdst[h * NN + dst];
    v = v > 0.0f ? v : 0.2f * v;                 // leaky_relu(0.2)
    g_ev[idx] = v;
    atomicMax(&g_emax[h * NN + dst], f2u_ord(v));
}

// ---------------- edge pass 2: exp + segment sum ----------------
__global__ void __launch_bounds__(256) edge_pass2(const void* __restrict__ ei) {
    int idx = blockIdx.x * 256 + threadIdx.x;
    if (idx >= NH * NE) return;
    int h = idx / NE;
    int e = idx - h * NE;
    int dst = load_idx(ei, g_ei64, NE + e);
    float m  = u2f_ord(g_emax[h * NN + dst]);
    float ex = __expf(g_ev[idx] - m);
    g_ev[idx] = ex;
    atomicAdd(&g_den[h * NN + dst], ex);
}

// ---------------- edge pass 3: fused 3-head weighted scatter ----------------
// one warp per edge; combine all heads in registers -> single red.v4 per lane.
__global__ void __launch_bounds__(256) edge_scatter(
    const void* __restrict__ ei, const void* __restrict__ eids,
    const float* __restrict__ ddi, const float* __restrict__ eemb,
    float* __restrict__ out)
{
    int w    = (blockIdx.x * 256 + threadIdx.x) >> 5;
    int lane = threadIdx.x & 31;
    if (w >= NE) return;
    int is64 = g_ei64;
    int src = load_idx(ei, is64, w);
    int dst = load_idx(ei, is64, NE + w);

    float c = 0.0f;
    if (lane < NH) {
        float ex  = g_ev[(size_t)lane * NE + w];
        float den = fmaxf(g_den[lane * NN + dst], 1e-16f);
        int   eid = load_idx(eids, g_eid64, w);
        float ew  = __ldg(eemb + eid) - __ldg(ddi + w);
        c = (ex / den) * ew * (1.0f / 3.0f);
    }
    float c0 = __shfl_sync(0xffffffffu, c, 0);
    float c1 = __shfl_sync(0xffffffffu, c, 1);
    float c2 = __shfl_sync(0xffffffffu, c, 2);

    float4 v0 = ((const float4*)(g_H + ((size_t)src) * D))[lane];
    float4 v1 = ((const float4*)(g_H + ((size_t)(NN + src)) * D))[lane];
    float4 v2 = ((const float4*)(g_H + ((size_t)(2 * NN + src)) * D))[lane];

    float4 r;
    r.x = fmaf(c2, v2.x, fmaf(c1, v1.x, c0 * v0.x));
    r.y = fmaf(c2, v2.y, fmaf(c1, v1.y, c0 * v0.y));
    r.z = fmaf(c2, v2.z, fmaf(c1, v1.z, c0 * v0.z));
    r.w = fmaf(c2, v2.w, fmaf(c1, v1.w, c0 * v0.w));

    float* op = out + (long long)dst * D + lane * 4;
    asm volatile("red.global.add.v4.f32 [%0], {%1,%2,%3,%4};"
                 :: "l"(op), "f"(r.x), "f"(r.y), "f"(r.z), "f"(r.w) : "memory");
}

// ---------------- launch ----------------
extern "C" void kernel_launch(void* const* d_in, const int* in_sizes, int n_in,
                              void* d_out, int out_size)
{
    const float* x    = (const float*)d_in[0];
    const void*  ei   = d_in[1];
    const void*  eids = d_in[2];
    const float* ddi  = (const float*)d_in[3];
    const float* Wlin = (const float*)d_in[4];
    const float* blin = (const float*)d_in[5];
    const float* eemb = (const float*)d_in[6];
    const float* Wh   = (const float*)d_in[7];
    const float* asrc = (const float*)d_in[8];
    const float* adst = (const float*)d_in[9];
    const float* bh   = (const float*)d_in[10];
    float* out = (float*)d_out;

    const int gemm_mblocks = (NN + 127) / 128;              // 391

    detect_dtype<<<1, 64>>>((const unsigned*)ei, (const unsigned*)eids);
    init_kernel<<<(NN * D + 255) / 256, 256>>>(out, bh);
    gemm_lin<<<gemm_mblocks, 256>>>(x, Wlin, blin);
    gemm_heads<<<dim3(gemm_mblocks, NH), 256>>>(Wh);
    attn_scores<<<(NH * NN * 32 + 255) / 256, 256>>>(asrc, adst);
    edge_pass1<<<(NH * NE + 255) / 256, 256>>>(ei);
    edge_pass2<<<(NH * NE + 255) / 256, 256>>>(ei);
    edge_scatter<<<(NE * 32 + 255) / 256, 256>>>(ei, eids, ddi, eemb, out);
}